// round 16
// baseline (speedup 1.0000x reference)
#include <cuda_runtime.h>
#include <cuda_bf16.h>

// MaxPool2d k=2 s=2 on fp32 NCHW (32, 96, 224, 224) -> (32, 96, 112, 112).
// DRAM-controller-bound at ~7.05 TB/s (88-89% of 8 TB/s spec); traffic is
// information-theoretically minimal (771 MB). All structural variants land
// within noise of 109.0-109.3 us. This round: final block-size probe
// (256 -> 109.31, 512 -> 109.02, now 1024): 9,408 blocks, 2 resident
// CTAs/SM = 64 warps/SM, everything else identical to the best kernel.
//
// Shape: one thread per output float4, 2x LDG.128 per input row + 1x STG.128
// (evict-first streaming hints); grid divides exactly (9,633,792 = 1024*9408)
// so no bounds check.

#define NC_    3072
#define W_     224
#define OH_    112
#define OW4_   28            // float4s per output row
#define ROWF4_ (W_ / 4)      // 56 float4s per input row
#define TOTAL_ (NC_ * OH_ * OW4_)   // 9,633,792 = 1024 * 9408 exactly

__global__ __launch_bounds__(1024)
void maxpool2x2_kernel(const float4* __restrict__ x, float4* __restrict__ out) {
    unsigned int idx = blockIdx.x * 1024u + threadIdx.x;   // == output float4 index

    unsigned int ox4 = idx % OW4_;           // float4 within output row
    unsigned int t   = idx / OW4_;
    unsigned int oy  = t % OH_;
    unsigned int nc  = t / OH_;

    // Input as float4 indices: plane = nc*12544, rows 2*oy / 2*oy+1, col 2*ox4.
    size_t base = (size_t)nc * (W_ * W_ / 4) + (size_t)(2u * oy) * ROWF4_ + 2u * ox4;

    float4 a0 = __ldcs(x + base);               // row 2*oy,   floats [8*ox4 .. +3]
    float4 a1 = __ldcs(x + base + 1);           // row 2*oy,   floats [+4 .. +7]
    float4 b0 = __ldcs(x + base + ROWF4_);      // row 2*oy+1, floats [8*ox4 .. +3]
    float4 b1 = __ldcs(x + base + ROWF4_ + 1);  // row 2*oy+1, floats [+4 .. +7]

    float4 r;
    r.x = fmaxf(fmaxf(a0.x, a0.y), fmaxf(b0.x, b0.y));
    r.y = fmaxf(fmaxf(a0.z, a0.w), fmaxf(b0.z, b0.w));
    r.z = fmaxf(fmaxf(a1.x, a1.y), fmaxf(b1.x, b1.y));
    r.w = fmaxf(fmaxf(a1.z, a1.w), fmaxf(b1.z, b1.w));

    __stcs(out + idx, r);
}

extern "C" void kernel_launch(void* const* d_in, const int* in_sizes, int n_in,
                              void* d_out, int out_size) {
    const float4* x = (const float4*)d_in[0];
    float4* out = (float4*)d_out;
    maxpool2x2_kernel<<<TOTAL_ / 1024, 1024>>>(x, out);
}